// round 4
// baseline (speedup 1.0000x reference)
#include <cuda_runtime.h>
#include <cuda_fp16.h>
#include <cstdint>

#define BATCH   64
#define SEQ     1024
#define IDIM    128
#define HDIM    512
#define G4      2048
#define KTOT    640
#define NGRP    4
#define GB      16
#define NCTA    32
#define HC      16
#define NL      64
#define THREADS 128
#define NCH_H   32
#define NCH_X   8

#define ZSTR 648
#define ASTR 648
#define OFF_Z   0
#define OFF_AH  (NL * ZSTR * 2)
#define SMEM_SZ (OFF_AH + GB * ASTR * 2)   // 103,680 B

__device__ __half g_xhi[BATCH * SEQ * IDIM];
__device__ __half g_hhi[2][BATCH][HDIM];
__device__ __half g_hlo[BATCH][HDIM];      // final step only (FC precision)
__device__ int    g_flag[NGRP][NCTA][32];  // 128B-padded flags
__device__ int    g_done[NGRP][NCTA];      // per-step warp-completion counters
__device__ int    g_cnt;
__device__ int    g_gen;

// ---- prologue-only global barrier (replay-safe) ------------------------------
__device__ __forceinline__ void bar_all(int n)
{
    int my;
    asm volatile("ld.acquire.gpu.global.b32 %0, [%1];" : "=r"(my) : "l"(&g_gen));
    __threadfence();
    if (atomicAdd(&g_cnt, 1) == n - 1) {
        atomicExch(&g_cnt, 0);
        __threadfence();
        atomicAdd(&g_gen, 1);
    } else {
        int v;
        do { asm volatile("ld.acquire.gpu.global.b32 %0, [%1];" : "=r"(v) : "l"(&g_gen)); }
        while (v == my);
    }
}

__device__ __forceinline__ void poll_flags(int grp, int lane, int need)
{
    const int* fp = &g_flag[grp][lane][0];
    int v;
    do { asm volatile("ld.acquire.gpu.global.b32 %0, [%1];" : "=r"(v) : "l"(fp)); }
    while (__any_sync(0xffffffffu, v < need));
}

__device__ __forceinline__ int atom_add_acqrel(int* p, int v)
{
    int old;
    asm volatile("atom.add.acq_rel.gpu.global.s32 %0, [%1], %2;"
                 : "=r"(old) : "l"(p), "r"(v) : "memory");
    return old;
}

__device__ __forceinline__ void cpasync16(uint32_t dst, const void* src)
{
    asm volatile("cp.async.cg.shared.global [%0], [%1], 16;" :: "r"(dst), "l"(src));
}
__device__ __forceinline__ void cpwait()
{
    asm volatile("cp.async.wait_all;" ::: "memory");
}

__device__ __forceinline__ void ldsm4(unsigned r[4], uint32_t a)
{
    asm volatile("ldmatrix.sync.aligned.m8n8.x4.shared.b16 {%0,%1,%2,%3}, [%4];"
                 : "=r"(r[0]), "=r"(r[1]), "=r"(r[2]), "=r"(r[3]) : "r"(a));
}
__device__ __forceinline__ void mma_f16(float* d, const unsigned* a, const unsigned* b)
{
    asm volatile(
        "mma.sync.aligned.m16n8k16.row.col.f32.f16.f16.f32 "
        "{%0,%1,%2,%3}, {%4,%5,%6,%7}, {%8,%9}, {%0,%1,%2,%3};\n"
        : "+f"(d[0]), "+f"(d[1]), "+f"(d[2]), "+f"(d[3])
        : "r"(a[0]), "r"(a[1]), "r"(a[2]), "r"(a[3]), "r"(b[0]), "r"(b[1]));
}

__device__ __forceinline__ float fsig(float x)  { return 1.f / (1.f + __expf(-x)); }
__device__ __forceinline__ float ftanh(float x) { return 1.f - 2.f / (__expf(2.f * x) + 1.f); }

// ---- x pre-split (hi only) ---------------------------------------------------
extern "C" __global__ void xsplit_kernel(const float* __restrict__ x)
{
    int idx = (blockIdx.x * 256 + threadIdx.x) * 4;
    float4 v = *(const float4*)(x + idx);
    *(__half2*)(g_xhi + idx)     = __halves2half2(__float2half(v.x), __float2half(v.y));
    *(__half2*)(g_xhi + idx + 2) = __halves2half2(__float2half(v.z), __float2half(v.w));
}

// ---- persistent LSTM ---------------------------------------------------------
extern "C" __global__ void __launch_bounds__(THREADS, 1)
lstm_kernel(const float* __restrict__ W, const float* __restrict__ U,
            const float* __restrict__ bias,
            const float* __restrict__ fc_w, const float* __restrict__ fc_b,
            float* __restrict__ out)
{
    extern __shared__ char smem[];
    __half* zh = (__half*)(smem + OFF_Z);

    const int tid  = threadIdx.x;
    const int lane = tid & 31;
    const int warp = tid >> 5;
    const int grp  = blockIdx.x >> 5;
    const int gc   = blockIdx.x & 31;
    const int b0   = grp * GB;
    const int h0   = gc * HC;
    const uint32_t smb = (uint32_t)__cvta_generic_to_shared(smem);

    // weights, gate-interleaved local cols: nl -> hid = nl>>2, gate = nl&3
    for (int idx = tid; idx < KTOT * NL; idx += THREADS) {
        int k = idx >> 6, nl = idx & 63;
        int col = (nl & 3) * HDIM + h0 + (nl >> 2);
        float v = (k < HDIM) ? U[(size_t)k * G4 + col]
                             : W[(size_t)(k - HDIM) * G4 + col];
        zh[nl * ZSTR + k] = __float2half(v);
    }
    // bias preloaded in accumulator layout: acc[t][j],[j+2] -> bias gate 2*(lane&1)+j
    const int q = (lane >> 1) & 1;
    float bv[2][2];
    #pragma unroll
    for (int t = 0; t < 2; t++) {
        int hid = h0 + warp * 4 + t * 2 + q;
        #pragma unroll
        for (int j = 0; j < 2; j++)
            bv[t][j] = bias[(2 * (lane & 1) + j) * HDIM + hid];
    }
    // stage x_0
    #pragma unroll
    for (int j = 0; j < 2; j++) {
        int i = tid + j * THREADS;
        int b = i >> 4, c8 = i & 15;
        size_t src = ((size_t)(b0 + b) * SEQ) * IDIM + c8 * 8;
        *(uint4*)(smem + OFF_AH + (b * ASTR + HDIM + c8 * 8) * 2) = *(const uint4*)(g_xhi + src);
    }
    if (tid == 0) { g_flag[grp][gc][0] = 0; g_done[grp][gc] = 0; }
    __syncthreads();
    if (tid == 0) bar_all(NGRP * NCTA);
    __syncthreads();

    // ldmatrix lane addresses (layout verified in R3)
    const uint32_t aHiA = smb + OFF_AH + (((lane & 15) * ASTR + ((lane >> 4) << 3)) << 1);
    const int brow = warp * 16 + ((lane & 7) | ((lane >> 1) & 8));
    const uint32_t bHiA = smb + OFF_Z + ((brow * ZSTR + (lane & 8)) << 1);

    const int r = lane >> 2;
    float c0 = 0.f, c1 = 0.f;

    for (int s = 0; s < SEQ; s++) {
        float acc[2][4];
        #pragma unroll
        for (int t = 0; t < 2; t++) {
            acc[t][0] = bv[t][0]; acc[t][1] = bv[t][1];
            acc[t][2] = bv[t][0]; acc[t][3] = bv[t][1];
        }

        // x-part GEMM (h-independent; hides producer->flag latency)
        #pragma unroll
        for (int kc = NCH_H; kc < NCH_H + NCH_X; kc++) {
            unsigned ah[4], bh[4];
            ldsm4(ah, aHiA + kc * 32);
            ldsm4(bh, bHiA + kc * 32);
            mma_f16(acc[0], ah, bh);
            mma_f16(acc[1], ah, bh + 2);
        }

        if (s > 0 && warp == 0) poll_flags(grp, lane, s);
        __syncthreads();   // poll done + all warps finished reading smem A

        // stage h_s and x_{s+1} via cp.async
        if (s > 0) {
            const __half* hs = &g_hhi[s & 1][b0][0];
            #pragma unroll
            for (int j = 0; j < 8; j++) {
                int i = tid + j * THREADS;          // 0..1023
                int b = i >> 6, c8 = i & 63;
                cpasync16(smb + OFF_AH + (b * ASTR + c8 * 8) * 2, hs + b * HDIM + c8 * 8);
            }
        }
        if (s + 1 < SEQ) {
            #pragma unroll
            for (int j = 0; j < 2; j++) {
                int i = tid + j * THREADS;
                int b = i >> 4, c8 = i & 15;
                cpasync16(smb + OFF_AH + (b * ASTR + HDIM + c8 * 8) * 2,
                          g_xhi + ((size_t)(b0 + b) * SEQ + (s + 1)) * IDIM + c8 * 8);
            }
        }
        cpwait();
        __syncthreads();

        // h-part GEMM
        if (s > 0) {
            #pragma unroll 8
            for (int kc = 0; kc < NCH_H; kc++) {
                unsigned ah[4], bh[4];
                ldsm4(ah, aHiA + kc * 32);
                ldsm4(bh, bHiA + kc * 32);
                mma_f16(acc[0], ah, bh);
                mma_f16(acc[1], ah, bh + 2);
            }
        }

        // register epilogue: pair exchange via shfl.xor 1 (bias already in acc)
        const int np = (s + 1) & 1;
        #pragma unroll
        for (int t = 0; t < 2; t++) {
            float e0 = __shfl_xor_sync(0xffffffffu, acc[t][0], 1);
            float e1 = __shfl_xor_sync(0xffffffffu, acc[t][1], 1);
            float e2 = __shfl_xor_sync(0xffffffffu, acc[t][2], 1);
            float e3 = __shfl_xor_sync(0xffffffffu, acc[t][3], 1);
            float gi, gf, gg, go;
            int bidx;
            if ((lane & 1) == 0) {
                gi = acc[t][0]; gf = acc[t][1]; gg = e0; go = e1; bidx = r;
            } else {
                gi = e2; gf = e3; gg = acc[t][2]; go = acc[t][3]; bidx = r + 8;
            }
            float i_ = fsig(gi), f_ = fsig(gf), g_ = ftanh(gg), o_ = fsig(go);
            float& cc = t ? c1 : c0;
            cc = f_ * cc + i_ * g_;
            float h = o_ * ftanh(cc);
            int ht = h0 + warp * 4 + t * 2 + q;
            __half hh = __float2half(h);
            g_hhi[np][b0 + bidx][ht] = hh;
            if (s == SEQ - 1)
                g_hlo[b0 + bidx][ht] = __float2half(h - __half2float(hh));
        }
        // early release: 4th warp to finish publishes the flag
        if (lane == 0) {
            int old = atom_add_acqrel(&g_done[grp][gc], 1);
            if (old == 4 * s + 3)
                asm volatile("st.release.gpu.global.b32 [%0], %1;"
                             :: "l"(&g_flag[grp][gc][0]), "r"(s + 1) : "memory");
        }
    }

    // FC head: one CTA per group (full-precision h = hi + lo)
    if (gc == 0) {
        if (warp == 0) poll_flags(grp, lane, SEQ);
        __syncthreads();
        int b = tid >> 3, l8 = tid & 7;
        float a7[7] = {0.f, 0.f, 0.f, 0.f, 0.f, 0.f, 0.f};
        for (int it = 0; it < HDIM / 8; it++) {
            int k = l8 + it * 8;
            float hv = __half2float(g_hhi[0][b0 + b][k]) + __half2float(g_hlo[b0 + b][k]);
            #pragma unroll
            for (int o = 0; o < 7; o++) a7[o] += hv * fc_w[k * 7 + o];
        }
        #pragma unroll
        for (int o = 0; o < 7; o++) {
            a7[o] += __shfl_xor_sync(0xffffffffu, a7[o], 4);
            a7[o] += __shfl_xor_sync(0xffffffffu, a7[o], 2);
            a7[o] += __shfl_xor_sync(0xffffffffu, a7[o], 1);
        }
        if (l8 == 0)
            #pragma unroll
            for (int o = 0; o < 7; o++) out[(b0 + b) * 7 + o] = a7[o] + fc_b[o];
    }
}

extern "C" void kernel_launch(void* const* d_in, const int* in_sizes, int n_in,
                              void* d_out, int out_size)
{
    (void)in_sizes; (void)n_in; (void)out_size;
    const float* x    = (const float*)d_in[0];
    const float* W    = (const float*)d_in[1];
    const float* U    = (const float*)d_in[2];
    const float* bias = (const float*)d_in[3];
    const float* fc_w = (const float*)d_in[4];
    const float* fc_b = (const float*)d_in[5];

    cudaFuncSetAttribute(lstm_kernel,
                         cudaFuncAttributeMaxDynamicSharedMemorySize, SMEM_SZ);
    xsplit_kernel<<<BATCH * SEQ * IDIM / 1024, 256>>>(x);
    lstm_kernel<<<NGRP * NCTA, THREADS, SMEM_SZ>>>(W, U, bias, fc_w, fc_b, (float*)d_out);
}